// round 1
// baseline (speedup 1.0000x reference)
#include <cuda_runtime.h>
#include <cuda_bf16.h>
#include <math.h>

// Problem constants
#define BS      4
#define SEQ     1024
#define DIM     1024
#define N_HEADS 16
#define D_HEAD  64
#define MROWS   (BS * SEQ)      // 4096

// ---------------------------------------------------------------------------
// Scratch (static device globals; no runtime allocation allowed)
// ---------------------------------------------------------------------------
__device__ float g_q  [MROWS * DIM];
__device__ float g_k  [MROWS * DIM];
__device__ float g_v  [MROWS * DIM];
__device__ float g_ctx[MROWS * DIM];

// ---------------------------------------------------------------------------
// SGEMM: C = alpha * (A @ B + bias)      A: MxK row-major, B: KxN row-major
// 128x128 block, BK=8, 8x8 per thread, 256 threads
// ---------------------------------------------------------------------------
#define BM 128
#define BN 128
#define BK 8
#define TM 8
#define TN 8

__global__ __launch_bounds__(256) void sgemm_bias_kernel(
    const float* __restrict__ A, const float* __restrict__ B,
    const float* __restrict__ bias, float* __restrict__ C,
    int M, int N, int K, float alpha)
{
    __shared__ float As[BK][BM];
    __shared__ float Bs[BK][BN];

    const int tid = threadIdx.x;
    const int bx  = blockIdx.x;   // N tile
    const int by  = blockIdx.y;   // M tile

    // A tile load: 128x8 = 1024 floats / 256 thr = one float4 each
    const int a_row = tid >> 1;          // 0..127
    const int a_col = (tid & 1) * 4;     // 0 or 4
    // B tile load: 8x128 = 1024 floats
    const int b_row = tid >> 5;          // 0..7
    const int b_col = (tid & 31) * 4;    // 0..124

    const float* Ab = A + (size_t)by * BM * K;
    const float* Bb = B + (size_t)bx * BN;

    const int trow = (tid >> 4) * TM;    // 0..120
    const int tcol = (tid & 15) * TN;    // 0..120

    float acc[TM][TN];
    #pragma unroll
    for (int i = 0; i < TM; i++)
        #pragma unroll
        for (int j = 0; j < TN; j++)
            acc[i][j] = 0.f;

    for (int k0 = 0; k0 < K; k0 += BK) {
        float4 av = *(const float4*)(Ab + (size_t)a_row * K + k0 + a_col);
        As[a_col + 0][a_row] = av.x;
        As[a_col + 1][a_row] = av.y;
        As[a_col + 2][a_row] = av.z;
        As[a_col + 3][a_row] = av.w;
        *(float4*)(&Bs[b_row][b_col]) =
            *(const float4*)(Bb + (size_t)(k0 + b_row) * N + b_col);
        __syncthreads();

        #pragma unroll
        for (int kk = 0; kk < BK; kk++) {
            float a_frag[TM], b_frag[TN];
            #pragma unroll
            for (int i = 0; i < TM; i += 4) {
                float4 t = *(const float4*)(&As[kk][trow + i]);
                a_frag[i + 0] = t.x; a_frag[i + 1] = t.y;
                a_frag[i + 2] = t.z; a_frag[i + 3] = t.w;
            }
            #pragma unroll
            for (int j = 0; j < TN; j += 4) {
                float4 t = *(const float4*)(&Bs[kk][tcol + j]);
                b_frag[j + 0] = t.x; b_frag[j + 1] = t.y;
                b_frag[j + 2] = t.z; b_frag[j + 3] = t.w;
            }
            #pragma unroll
            for (int i = 0; i < TM; i++)
                #pragma unroll
                for (int j = 0; j < TN; j++)
                    acc[i][j] = fmaf(a_frag[i], b_frag[j], acc[i][j]);
        }
        __syncthreads();
    }

    // epilogue: alpha * (acc + bias)
    #pragma unroll
    for (int i = 0; i < TM; i++) {
        const int row = by * BM + trow + i;
        #pragma unroll
        for (int j = 0; j < TN; j += 4) {
            float4 bv = *(const float4*)(bias + bx * BN + tcol + j);
            float4 cv;
            cv.x = alpha * (acc[i][j + 0] + bv.x);
            cv.y = alpha * (acc[i][j + 1] + bv.y);
            cv.z = alpha * (acc[i][j + 2] + bv.z);
            cv.w = alpha * (acc[i][j + 3] + bv.w);
            *(float4*)(C + (size_t)row * N + bx * BN + tcol + j) = cv;
        }
    }
}

// ---------------------------------------------------------------------------
// Flash attention with fused gauss reweight.
// softmax(s)*g / sum(softmax(s)*g) == exp(s - m)*g / sum(exp(s - m)*g),
// so g folds into the online-softmax weights directly.
// One thread = one query row. 128 rows / block. K/V tiles of 32 keys in smem.
// Q,K,V layout: (b*SEQ + s, DIM) row-major; head h occupies cols [h*64, h*64+64)
// grid: (SEQ/128, N_HEADS, BS)
// ---------------------------------------------------------------------------
#define TILE_K 32

__global__ __launch_bounds__(128) void flash_attn_kernel(
    const int* __restrict__ mask, const float* __restrict__ gauss)
{
    __shared__ float Ks[TILE_K][D_HEAD];
    __shared__ float Vs[TILE_K][D_HEAD];
    __shared__ float Gs[TILE_K];

    const int tid = threadIdx.x;
    const int b   = blockIdx.z;
    const int h   = blockIdx.y;
    const int row = blockIdx.x * 128 + tid;   // query position in [0, SEQ)

    // load q row (64 floats) into registers
    float4 q4[D_HEAD / 4];
    {
        const float* qp = g_q + ((size_t)(b * SEQ + row)) * DIM + h * D_HEAD;
        #pragma unroll
        for (int i = 0; i < D_HEAD / 4; i++)
            q4[i] = *(const float4*)(qp + i * 4);
    }

    float m = -1e30f, l = 0.f;
    float o[D_HEAD];
    #pragma unroll
    for (int d = 0; d < D_HEAD; d++) o[d] = 0.f;

    for (int kt = 0; kt < SEQ; kt += TILE_K) {
        // cooperative tile load: 32*64 floats each for K and V, float4s
        {
            const float* kbase = g_k + ((size_t)(b * SEQ + kt)) * DIM + h * D_HEAD;
            const float* vbase = g_v + ((size_t)(b * SEQ + kt)) * DIM + h * D_HEAD;
            #pragma unroll
            for (int i = 0; i < 4; i++) {
                int off = (i * 128 + tid) * 4;     // flat float offset in tile
                int j = off >> 6;                   // key within tile
                int d = off & 63;
                *(float4*)(&Ks[j][d]) = *(const float4*)(kbase + (size_t)j * DIM + d);
                *(float4*)(&Vs[j][d]) = *(const float4*)(vbase + (size_t)j * DIM + d);
            }
            if (tid < TILE_K) {
                int kk = kt + tid;
                float g = gauss[b * SEQ + kk] + 1e-10f;
                // fold the mask into g: masked key -> weight forced to 0 and
                // score left intact (exp stays finite; contribution is 0)
                Gs[tid] = (mask[b * SEQ + kk] == 0) ? 0.f : g;
            }
        }
        __syncthreads();

        // pass 1: scores for all 32 keys
        float s[TILE_K];
        float tmax = -1e30f;
        #pragma unroll
        for (int j = 0; j < TILE_K; j++) {
            float acc = 0.f;
            #pragma unroll
            for (int i = 0; i < D_HEAD / 4; i++) {
                float4 kv = *(const float4*)(&Ks[j][i * 4]);
                acc = fmaf(q4[i].x, kv.x, acc);
                acc = fmaf(q4[i].y, kv.y, acc);
                acc = fmaf(q4[i].z, kv.z, acc);
                acc = fmaf(q4[i].w, kv.w, acc);
            }
            // keys with zero gauss-weight (masked) cannot raise the max;
            // since g==0 kills them anyway, only exclude them from max
            s[j] = acc;
            float eff = (Gs[j] == 0.f) ? -1e30f : acc;
            tmax = fmaxf(tmax, eff);
        }

        const float mnew  = fmaxf(m, tmax);
        const float scale = __expf(m - mnew);
        l *= scale;
        #pragma unroll
        for (int d = 0; d < D_HEAD; d++) o[d] *= scale;

        // pass 2: accumulate
        #pragma unroll
        for (int j = 0; j < TILE_K; j++) {
            float p = __expf(s[j] - mnew) * Gs[j];
            l += p;
            #pragma unroll
            for (int d = 0; d < D_HEAD; d += 4) {
                float4 vv = *(const float4*)(&Vs[j][d]);
                o[d + 0] = fmaf(p, vv.x, o[d + 0]);
                o[d + 1] = fmaf(p, vv.y, o[d + 1]);
                o[d + 2] = fmaf(p, vv.z, o[d + 2]);
                o[d + 3] = fmaf(p, vv.w, o[d + 3]);
            }
        }
        m = mnew;
        __syncthreads();
    }

    const float inv_l = 1.f / l;
    float* op = g_ctx + ((size_t)(b * SEQ + row)) * DIM + h * D_HEAD;
    #pragma unroll
    for (int d = 0; d < D_HEAD; d += 4) {
        float4 cv;
        cv.x = o[d + 0] * inv_l;
        cv.y = o[d + 1] * inv_l;
        cv.z = o[d + 2] * inv_l;
        cv.w = o[d + 3] * inv_l;
        *(float4*)(op + d) = cv;
    }
}

// ---------------------------------------------------------------------------
// Launch
// inputs: 0=query 1=key 2=value 3=mask 4=gauss_weight
//         5=Wq 6=bq 7=Wk 8=bk 9=Wv 10=bv 11=Wo 12=bo
// ---------------------------------------------------------------------------
extern "C" void kernel_launch(void* const* d_in, const int* in_sizes, int n_in,
                              void* d_out, int out_size)
{
    const float* query = (const float*)d_in[0];
    const float* key   = (const float*)d_in[1];
    const float* value = (const float*)d_in[2];
    const int*   mask  = (const int*)  d_in[3];
    const float* gauss = (const float*)d_in[4];
    const float* Wq = (const float*)d_in[5];
    const float* bq = (const float*)d_in[6];
    const float* Wk = (const float*)d_in[7];
    const float* bk = (const float*)d_in[8];
    const float* Wv = (const float*)d_in[9];
    const float* bv = (const float*)d_in[10];
    const float* Wo = (const float*)d_in[11];
    const float* bo = (const float*)d_in[12];
    float* out = (float*)d_out;

    float *pq, *pk, *pv, *pctx;
    cudaGetSymbolAddress((void**)&pq,   g_q);
    cudaGetSymbolAddress((void**)&pk,   g_k);
    cudaGetSymbolAddress((void**)&pv,   g_v);
    cudaGetSymbolAddress((void**)&pctx, g_ctx);

    dim3 ggrid(DIM / BN, MROWS / BM);   // (8, 32)
    const float qscale = 1.0f / 8.0f;   // 1/sqrt(D_HEAD)

    sgemm_bias_kernel<<<ggrid, 256>>>(query, Wq, bq, pq, MROWS, DIM, DIM, qscale);
    sgemm_bias_kernel<<<ggrid, 256>>>(key,   Wk, bk, pk, MROWS, DIM, DIM, 1.0f);
    sgemm_bias_kernel<<<ggrid, 256>>>(value, Wv, bv, pv, MROWS, DIM, DIM, 1.0f);

    dim3 agrid(SEQ / 128, N_HEADS, BS); // (8, 16, 4)
    flash_attn_kernel<<<agrid, 128>>>(mask, gauss);

    sgemm_bias_kernel<<<ggrid, 256>>>(pctx, Wo, bo, out, MROWS, DIM, DIM, 1.0f);
}